// round 3
// baseline (speedup 1.0000x reference)
#include <cuda_runtime.h>

// Problem constants
#define NN 2
#define RR 65536
#define KK 64
#define CC 16
#define NRAYS (NN*RR)          // 131072
#define KM1 63

// Output layout: tuple flattened in order
#define OFF_CC 0
#define OFF_RD (NRAYS*CC)              // 2,097,152
#define OFF_W  (OFF_RD + NRAYS)        // 2,228,224
#define OFF_TE (OFF_W + NRAYS*KM1)     // 10,485,760

#define RAYS_PER_BLOCK 16
#define THREADS 256

__device__ int g_min_bits;
__device__ int g_max_bits;

// ---------------------------------------------------------------------------
// Kernel 0: reset global min/max (must run every replay — graph-deterministic)
// ---------------------------------------------------------------------------
__global__ void init_minmax_kernel() {
    g_min_bits = 0x7f7fffff;   // FLT_MAX (all radii positive)
    g_max_bits = 0;            // 0.0f
}

// ---------------------------------------------------------------------------
// Kernel 1: global min/max over radii midpoints. radii sorted along K, so
// per-ray min midpoint = 0.5*(r0+r1), max = 0.5*(r62+r63).
// ---------------------------------------------------------------------------
__global__ void minmax_kernel(const float* __restrict__ radii) {
    int ray = blockIdx.x * blockDim.x + threadIdx.x;
    float mn = 3.402823466e38f;
    float mx = 0.0f;
    if (ray < NRAYS) {
        float2 lo = *(const float2*)(radii + ray * KK);
        float2 hi = *(const float2*)(radii + ray * KK + (KK - 2));
        mn = 0.5f * (lo.x + lo.y);
        mx = 0.5f * (hi.x + hi.y);
    }
    // warp reduce
    #pragma unroll
    for (int o = 16; o > 0; o >>= 1) {
        mn = fminf(mn, __shfl_xor_sync(0xffffffffu, mn, o));
        mx = fmaxf(mx, __shfl_xor_sync(0xffffffffu, mx, o));
    }
    __shared__ float smn[8], smx[8];
    int w = threadIdx.x >> 5, l = threadIdx.x & 31;
    if (l == 0) { smn[w] = mn; smx[w] = mx; }
    __syncthreads();
    if (threadIdx.x == 0) {
        #pragma unroll
        for (int i = 1; i < 8; i++) {
            mn = fminf(mn, smn[i]);
            mx = fmaxf(mx, smx[i]);
        }
        // positive floats: int ordering == float ordering
        atomicMin(&g_min_bits, __float_as_int(mn));
        atomicMax(&g_max_bits, __float_as_int(mx));
    }
}

// ---------------------------------------------------------------------------
// Kernel 2: main compositing. 16 threads per ray (lane = channel),
// 16 rays per 256-thread block.
// ---------------------------------------------------------------------------
__global__ __launch_bounds__(THREADS)
void composite_kernel(const float* __restrict__ colors,
                      const float* __restrict__ densities,
                      const float* __restrict__ radii,
                      float* __restrict__ out) {
    __shared__ float s_r[RAYS_PER_BLOCK * 65];   // padded rows: conflict-free
    __shared__ float s_d[RAYS_PER_BLOCK * 65];
    __shared__ float s_w[RAYS_PER_BLOCK * KM1];  // matches output flat layout

    const int tid = threadIdx.x;
    const int blk_ray0 = blockIdx.x * RAYS_PER_BLOCK;

    // Cooperative load of radii + densities for 16 rays (1024 floats each)
    {
        const float4* rg = (const float4*)(radii + (size_t)blk_ray0 * KK);
        const float4* dg = (const float4*)(densities + (size_t)blk_ray0 * KK);
        float4 rv = rg[tid];
        float4 dv = dg[tid];
        int ray = (tid * 4) >> 6;     // which ray within block
        int off = (tid * 4) & 63;     // offset within ray
        float* pr = s_r + ray * 65 + off;
        float* pd = s_d + ray * 65 + off;
        pr[0] = rv.x; pr[1] = rv.y; pr[2] = rv.z; pr[3] = rv.w;
        pd[0] = dv.x; pd[1] = dv.y; pd[2] = dv.z; pd[3] = dv.w;
    }
    __syncthreads();

    const int rin = tid >> 4;        // ray within block: 0..15
    const int c   = tid & 15;        // channel: 0..15
    const int ray = blk_ray0 + rin;

    const float* colp = colors + (size_t)ray * (KK * CC) + c;
    const float* sr = s_r + rin * 65;
    const float* sd = s_d + rin * 65;
    float* sw = s_w + rin * KM1;

    float T = 1.0f, Tprev = 1.0f;
    float col_acc = 0.0f, wsum = 0.0f, rsum = 0.0f;
    float cprev = __ldg(colp);
    float r0 = sr[0], d0 = sd[0];

    #pragma unroll 7
    for (int k = 0; k < KM1; k++) {
        float cnext = __ldg(colp + (k + 1) * CC);
        float r1 = sr[k + 1];
        float d1 = sd[k + 1];
        float delta = r1 - r0;
        float dm = fmaxf(0.5f * (d0 + d1), 0.0f);
        float rm = 0.5f * (r0 + r1);
        float e = __expf(-delta * dm);
        float alpha = 1.0f - e;
        Tprev = T;
        float w = alpha * T;
        T = T * (1.0f - alpha + 1e-10f);
        col_acc += w * (0.5f * (cprev + cnext));
        wsum += w;
        rsum += w * rm;
        if (c == 0) sw[k] = w;
        cprev = cnext; r0 = r1; d0 = d1;
    }

    // composite_color: (N*R, C) — full-warp 128B coalesced store
    out[OFF_CC + (size_t)ray * CC + c] = col_acc * 2.0f - 1.0f;

    if (c == 0) {
        float gmin = __int_as_float(g_min_bits);
        float gmax = __int_as_float(g_max_bits);
        float cr = rsum / wsum;                 // 0/0 -> nan, x/0 -> inf
        if (cr != cr) cr = __int_as_float(0x7f800000);  // nan -> +inf
        cr = fminf(fmaxf(cr, gmin), gmax);
        out[OFF_RD + ray] = cr;
        out[OFF_TE + ray] = Tprev;              // T_end = T[62] (pre last mult)
    }

    __syncthreads();   // all half-warps finished writing s_w

    // weights: block region is exactly contiguous 1008 floats in output
    float* wout = out + OFF_W + (size_t)blk_ray0 * KM1;
    #pragma unroll
    for (int i = tid; i < RAYS_PER_BLOCK * KM1; i += THREADS)
        wout[i] = s_w[i];
}

// ---------------------------------------------------------------------------
extern "C" void kernel_launch(void* const* d_in, const int* in_sizes, int n_in,
                              void* d_out, int out_size) {
    const float* colors    = (const float*)d_in[0];
    const float* densities = (const float*)d_in[1];
    const float* radii     = (const float*)d_in[2];
    float* out = (float*)d_out;

    init_minmax_kernel<<<1, 1>>>();
    minmax_kernel<<<(NRAYS + 255) / 256, 256>>>(radii);
    composite_kernel<<<NRAYS / RAYS_PER_BLOCK, THREADS>>>(colors, densities,
                                                          radii, out);
}